// round 15
// baseline (speedup 1.0000x reference)
#include <cuda_runtime.h>
#include <cuda_fp16.h>
#include <math.h>
#include <stdint.h>

// Problem constants
#define N_B 8
#define LQ 4096
#define CDIM 768
#define HH 8
#define PP 4
#define DD 96
#define LIN 1728
#define NVOX 12

// ---------------------------------------------------------------------------
// Scratch (static __device__ arrays: allocation-free, graph-capture safe)
// ---------------------------------------------------------------------------
__device__ __half g_inph[(size_t)N_B * LIN * CDIM];      // input_flatten (fp16)
__device__ __half g_valh[(size_t)N_B * LIN * CDIM];      // value (fp16) 21.2 MB
__device__ float g_oa[(size_t)N_B * LQ * 128];           // fused offsets(96)+attn(32)
__device__ __half g_samp[(size_t)N_B * LQ * CDIM];       // sampled (fp16)

// pre-transposed fp16 weights: [N][K]
__device__ __half g_wv[CDIM * CDIM];
__device__ __half g_wo[CDIM * CDIM];
__device__ __half g_woa[128 * CDIM];   // rows 0..95 = w_off, 96..127 = w_att

// ---------------------------------------------------------------------------
// PTX helpers (baseline ISA: ldmatrix + mma.sync + cp.async, sm_80+)
// ---------------------------------------------------------------------------
__device__ __forceinline__ uint32_t smem_u32(const void* p) {
    uint32_t a;
    asm("{ .reg .u64 t; cvta.to.shared.u64 t, %1; cvt.u32.u64 %0, t; }" : "=r"(a) : "l"(p));
    return a;
}
__device__ __forceinline__ void ldmx4(uint32_t& r0, uint32_t& r1, uint32_t& r2,
                                      uint32_t& r3, uint32_t addr) {
    asm volatile("ldmatrix.sync.aligned.m8n8.x4.shared.b16 {%0,%1,%2,%3}, [%4];"
                 : "=r"(r0), "=r"(r1), "=r"(r2), "=r"(r3) : "r"(addr));
}
__device__ __forceinline__ void mma16816(float* d, const uint32_t* a, const uint32_t* b) {
    asm volatile(
        "mma.sync.aligned.m16n8k16.row.col.f32.f16.f16.f32 "
        "{%0,%1,%2,%3}, {%4,%5,%6,%7}, {%8,%9}, {%0,%1,%2,%3};"
        : "+f"(d[0]), "+f"(d[1]), "+f"(d[2]), "+f"(d[3])
        : "r"(a[0]), "r"(a[1]), "r"(a[2]), "r"(a[3]), "r"(b[0]), "r"(b[1]));
}
__device__ __forceinline__ void cpasync16(uint32_t dst, const void* src) {
    asm volatile("cp.async.cg.shared.global [%0], [%1], 16;" :: "r"(dst), "l"(src));
}
#define CP_COMMIT() asm volatile("cp.async.commit_group;" ::: "memory")
#define CP_WAIT(n)  asm volatile("cp.async.wait_group %0;" :: "n"(n) : "memory")

__device__ __forceinline__ uint32_t cvt2(float x, float y) {
    __half2 h = __floats2half2_rn(x, y);
    return *reinterpret_cast<uint32_t*>(&h);
}

// ---------------------------------------------------------------------------
// Bulk fp32 -> fp16 convert (8 elems/thread, vectorized)
// ---------------------------------------------------------------------------
__global__ void f2h(const float* __restrict__ in, __half* __restrict__ out, int n)
{
    int i = (blockIdx.x * 256 + threadIdx.x) * 8;
    if (i >= n) return;
    float4 a = *reinterpret_cast<const float4*>(in + i);
    float4 b = *reinterpret_cast<const float4*>(in + i + 4);
    uint4 o;
    o.x = cvt2(a.x, a.y);
    o.y = cvt2(a.z, a.w);
    o.z = cvt2(b.x, b.y);
    o.w = cvt2(b.z, b.w);
    *reinterpret_cast<uint4*>(out + i) = o;
}

// ---------------------------------------------------------------------------
// Coalesced tiled transpose + fp16 convert: h[n*K+k] = (half)w[k*N+n]
// ---------------------------------------------------------------------------
__device__ __forceinline__ void transpose_body(const float* __restrict__ w,
                                               __half* __restrict__ h, int K, int N)
{
    __shared__ float tile[32][33];
    const int k0 = blockIdx.x * 32, n0 = blockIdx.y * 32;
    const int tx = threadIdx.x, ty = threadIdx.y;
    #pragma unroll
    for (int i = 0; i < 32; i += 8)
        tile[ty + i][tx] = w[(size_t)(k0 + ty + i) * N + n0 + tx];
    __syncthreads();
    #pragma unroll
    for (int i = 0; i < 32; i += 8)
        h[(size_t)(n0 + ty + i) * K + k0 + tx] = __float2half(tile[tx][ty + i]);
}
__global__ void transpose_h(const float* __restrict__ w, __half* __restrict__ h,
                            int K, int N)
{
    transpose_body(w, h, K, N);
}
__global__ void transpose_h2(const float* __restrict__ w0, __half* __restrict__ h0,
                             const float* __restrict__ w1, __half* __restrict__ h1)
{
    transpose_body(blockIdx.z ? w1 : w0, blockIdx.z ? h1 : h0, CDIM, CDIM);
}

// ---------------------------------------------------------------------------
// fp16 HMMA GEMM: C[M,N] = A[M,K] @ Bt[N,K]^T + bias
// BM=128, BN=128, BK=32; 256 threads = 4(m) x 2(n) warps; warp tile 32x64.
// PRE=false: A fp32 converted inline, 2D grid (one tile per block).
// PRE=true : A fp16, persistent 1D grid with a CONTINUOUS cross-tile
//            4-stage cp.async pipeline (never drains between tiles).
// ---------------------------------------------------------------------------
template <bool PRE, bool OUTH>
__global__ void __launch_bounds__(256, 2)
gemm_mma(const float* __restrict__ A32, const __half* __restrict__ Ah,
         const __half* __restrict__ Bt,
         const float* __restrict__ bias, const float* __restrict__ bias2, int nsplit,
         void* __restrict__ Cout, int M, int N, int K)
{
    constexpr int BM = 128, BN = 128, BK = 32, SA = 40;
    constexpr int WN = BN / 2, NF = WN / 8;
    constexpr int A_ELE = BM * SA;
    constexpr int B_ELE = BN * SA;
    constexpr int BUF = A_ELE + B_ELE;

    extern __shared__ __half smbuf[];
    const uint32_t sbase = smem_u32(smbuf);

    const int tid = threadIdx.x;
    const int lane = tid & 31;
    const int wid = tid >> 5;
    const int wm = wid & 3, wn = wid >> 2;
    const int nch = K / BK;            // 24 for K=768 (multiple of 4)

    float acc[2][NF][4];
    float4 aR[4];

    auto asyncAB = [&](int bm, int bn, int c, int buf) {
        const int k0 = c * BK;
        const uint32_t base = sbase + (uint32_t)buf * BUF * 2;
        #pragma unroll
        for (int t = 0; t < 2; t++) {
            int l = t * 256 + tid;
            int rr = l >> 2, q = l & 3;
            uint32_t dstA = base + (uint32_t)(rr * SA + q * 8) * 2;
            cpasync16(dstA, &Ah[(size_t)(bm + rr) * K + k0 + q * 8]);
            uint32_t dstB = base + (uint32_t)(A_ELE + rr * SA + q * 8) * 2;
            cpasync16(dstB, &Bt[(size_t)(bn + rr) * K + k0 + q * 8]);
        }
    };
    auto asyncB = [&](int bn, int c, int buf) {
        const int k0 = c * BK;
        const uint32_t base = sbase + (uint32_t)buf * BUF * 2;
        #pragma unroll
        for (int t = 0; t < 2; t++) {
            int l = t * 256 + tid;
            int rr = l >> 2, q = l & 3;
            uint32_t dst = base + (uint32_t)(A_ELE + rr * SA + q * 8) * 2;
            cpasync16(dst, &Bt[(size_t)(bn + rr) * K + k0 + q * 8]);
        }
    };
    auto loadA = [&](int bm, int c) {
        const int k0 = c * BK;
        #pragma unroll
        for (int t = 0; t < 4; t++) {
            int l = t * 256 + tid;
            int row = l >> 3, c4 = l & 7;
            aR[t] = *reinterpret_cast<const float4*>(&A32[(size_t)(bm + row) * K + k0 + c4 * 4]);
        }
    };
    auto stsA = [&](int buf) {
        const uint32_t base = sbase + (uint32_t)buf * BUF * 2;
        #pragma unroll
        for (int t = 0; t < 4; t++) {
            int l = t * 256 + tid;
            int row = l >> 3, c4 = l & 7;
            uint32_t a01 = cvt2(aR[t].x, aR[t].y);
            uint32_t a23 = cvt2(aR[t].z, aR[t].w);
            uint32_t off = (uint32_t)(row * SA + c4 * 4) * 2;
            asm volatile("st.shared.v2.b32 [%0], {%1,%2};"
                         :: "r"(base + off), "r"(a01), "r"(a23) : "memory");
        }
    };
    auto compute = [&](int buf) {
        const uint32_t base = sbase + (uint32_t)buf * BUF * 2;
        const uint32_t aS = base;
        const uint32_t bS = base + A_ELE * 2;
        #pragma unroll
        for (int s = 0; s < 2; s++) {
            uint32_t ah[2][4], bh[NF][2];
            #pragma unroll
            for (int i = 0; i < 2; i++) {
                uint32_t row = wm * 32 + i * 16 + (lane & 15);
                uint32_t off = (row * SA + s * 16 + (lane >> 4) * 8) * 2;
                ldmx4(ah[i][0], ah[i][1], ah[i][2], ah[i][3], aS + off);
            }
            #pragma unroll
            for (int j = 0; j < NF; j += 2) {
                uint32_t row = wn * WN + j * 8 + (lane & 7) + ((lane & 16) ? 8 : 0);
                uint32_t off = (row * SA + s * 16 + ((lane >> 3) & 1) * 8) * 2;
                ldmx4(bh[j][0], bh[j][1], bh[j + 1][0], bh[j + 1][1], bS + off);
            }
            #pragma unroll
            for (int i = 0; i < 2; i++)
                #pragma unroll
                for (int j = 0; j < NF; j++)
                    mma16816(acc[i][j], ah[i], bh[j]);
        }
    };
    auto zeroAcc = [&]() {
        #pragma unroll
        for (int i = 0; i < 2; i++)
            #pragma unroll
            for (int j = 0; j < NF; j++)
                #pragma unroll
                for (int q = 0; q < 4; q++) acc[i][j][q] = 0.f;
    };
    auto epilogue = [&](int bm, int bn) {
        #pragma unroll
        for (int i = 0; i < 2; i++) {
            int r0 = bm + wm * 32 + i * 16 + (lane >> 2);
            #pragma unroll
            for (int j = 0; j < NF; j++) {
                int col = bn + wn * WN + j * 8 + (lane & 3) * 2;
                float b0 = (col < nsplit) ? bias[col] : bias2[col - nsplit];
                float b1 = (col + 1 < nsplit) ? bias[col + 1] : bias2[col + 1 - nsplit];
                if constexpr (OUTH) {
                    __half* C = (__half*)Cout;
                    uint32_t v0 = cvt2(acc[i][j][0] + b0, acc[i][j][1] + b1);
                    uint32_t v1 = cvt2(acc[i][j][2] + b0, acc[i][j][3] + b1);
                    *reinterpret_cast<uint32_t*>(&C[(size_t)r0 * N + col]) = v0;
                    *reinterpret_cast<uint32_t*>(&C[(size_t)(r0 + 8) * N + col]) = v1;
                } else {
                    float* C = (float*)Cout;
                    float2 v0 = make_float2(acc[i][j][0] + b0, acc[i][j][1] + b1);
                    float2 v1 = make_float2(acc[i][j][2] + b0, acc[i][j][3] + b1);
                    *reinterpret_cast<float2*>(&C[(size_t)r0 * N + col]) = v0;
                    *reinterpret_cast<float2*>(&C[(size_t)(r0 + 8) * N + col]) = v1;
                }
            }
        }
    };

    if constexpr (PRE) {
        // Persistent with continuous cross-tile pipeline. Stage = g % 4,
        // where g is the block's global chunk index; nch % 4 == 0 keeps
        // stage alignment consistent across tiles.
        const int ntn = N / BN;
        const int ntiles = (M / BM) * ntn;
        const int myTiles = (ntiles - (int)blockIdx.x + (int)gridDim.x - 1) / (int)gridDim.x;
        if (myTiles <= 0) return;
        const int totalChunks = myTiles * nch;

        auto issue = [&](int g) {
            int k = g / nch, c = g - k * nch;
            int t = (int)blockIdx.x + k * (int)gridDim.x;
            int bm = (t / ntn) * BM, bn = (t - (t / ntn) * ntn) * BN;
            asyncAB(bm, bn, c, g & 3);
        };

        // prologue: 3 stages in flight (totalChunks >= nch = 24 > 3)
        #pragma unroll
        for (int i = 0; i < 3; i++) { issue(i); CP_COMMIT(); }

        zeroAcc();
        for (int g = 0; g < totalChunks; g++) {
            CP_WAIT(2);
            __syncthreads();
            if (g + 3 < totalChunks) issue(g + 3);
            CP_COMMIT();
            compute(g & 3);
            int c = g % nch;
            if (c == nch - 1) {
                int k = g / nch;
                int t = (int)blockIdx.x + k * (int)gridDim.x;
                epilogue((t / ntn) * BM, (t - (t / ntn) * ntn) * BN);
                zeroAcc();
            }
        }
    } else {
        const int bm = blockIdx.y * BM, bn = blockIdx.x * BN;
        zeroAcc();
        asyncB(bn, 0, 0); CP_COMMIT();
        loadA(bm, 0);
        CP_WAIT(0);
        stsA(0);
        __syncthreads();
        for (int c = 0; c < nch; c++) {
            if (c + 1 < nch) { asyncB(bn, c + 1, (c + 1) & 1); CP_COMMIT(); loadA(bm, c + 1); }
            compute(c & 1);
            if (c + 1 < nch) { CP_WAIT(0); stsA((c + 1) & 1); }
            __syncthreads();
        }
        epilogue(bm, bn);
    }
}

// ---------------------------------------------------------------------------
// Sampler: 384 threads = 4 queries x 96 gather threads (uint4 = 8 fp16 ch).
// ---------------------------------------------------------------------------
__global__ void __launch_bounds__(384) sample_kernel(const float* __restrict__ refpts)
{
    const int b0 = blockIdx.x * 4;

    __shared__ float s_attn[4][32];
    __shared__ int   s_idx[4][32][8];
    __shared__ float s_w[4][32][8];

    const int tid = threadIdx.x;

    if (tid < 128) {
        int qi = tid >> 5, hp = tid & 31;
        int bq = b0 + qi;
        const float* oa = &g_oa[(size_t)bq * 128 + hp * 3];
        float rx = refpts[(size_t)bq * 3 + 0];
        float ry = refpts[(size_t)bq * 3 + 1];
        float rz = refpts[(size_t)bq * 3 + 2];
        float x = 12.f * rx + oa[0] - 0.5f;
        float y = 12.f * ry + oa[1] - 0.5f;
        float z = 12.f * rz + oa[2] - 0.5f;
        float x0f = floorf(x), y0f = floorf(y), z0f = floorf(z);
        int x0 = (int)x0f, y0 = (int)y0f, z0 = (int)z0f;
        float fx = x - x0f, fy = y - y0f, fz = z - z0f;
        #pragma unroll
        for (int c = 0; c < 8; c++) {
            int dx = c & 1, dy = (c >> 1) & 1, dz = (c >> 2) & 1;
            int xi = x0 + dx, yi = y0 + dy, zi = z0 + dz;
            float w = (dx ? fx : 1.f - fx) * (dy ? fy : 1.f - fy) * (dz ? fz : 1.f - fz);
            bool valid = (xi >= 0) & (xi < NVOX) & (yi >= 0) & (yi < NVOX) &
                         (zi >= 0) & (zi < NVOX);
            int xc = min(max(xi, 0), NVOX - 1);
            int yc = min(max(yi, 0), NVOX - 1);
            int zc = min(max(zi, 0), NVOX - 1);
            s_idx[qi][hp][c] = (zc * NVOX + yc) * NVOX + xc;
            s_w[qi][hp][c] = valid ? w : 0.f;
        }
    }
    if (tid >= 128 && tid < 160) {
        int idx = tid - 128;
        int qi = idx >> 3, h = idx & 7;
        const float* lg = &g_oa[(size_t)(b0 + qi) * 128 + 96 + h * 4];
        float m = fmaxf(fmaxf(lg[0], lg[1]), fmaxf(lg[2], lg[3]));
        float e0 = expf(lg[0] - m), e1 = expf(lg[1] - m);
        float e2 = expf(lg[2] - m), e3 = expf(lg[3] - m);
        float inv = 1.f / (e0 + e1 + e2 + e3);
        s_attn[qi][h * 4 + 0] = e0 * inv;
        s_attn[qi][h * 4 + 1] = e1 * inv;
        s_attn[qi][h * 4 + 2] = e2 * inv;
        s_attn[qi][h * 4 + 3] = e3 * inv;
    }
    __syncthreads();

    const int qi = tid / 96;
    const int tt = tid % 96;
    const int h = tt / 12;
    const int c8 = (tt % 12) * 8;
    const int bq = b0 + qi;
    const int n = bq >> 12;
    const __half* vbase = &g_valh[(size_t)n * LIN * CDIM + h * DD + c8];

    float acc[8];
    #pragma unroll
    for (int k = 0; k < 8; k++) acc[k] = 0.f;

    #pragma unroll
    for (int p = 0; p < PP; p++) {
        int hp = h * PP + p;
        float a = s_attn[qi][hp];
        float sv[8];
        #pragma unroll
        for (int k = 0; k < 8; k++) sv[k] = 0.f;
        #pragma unroll
        for (int c = 0; c < 8; c++) {
            float w = s_w[qi][hp][c];
            uint4 v = *reinterpret_cast<const uint4*>(
                vbase + (size_t)s_idx[qi][hp][c] * CDIM);
            const __half2* hv = reinterpret_cast<const __half2*>(&v);
            #pragma unroll
            for (int k = 0; k < 4; k++) {
                float2 f = __half22float2(hv[k]);
                sv[2 * k]     = fmaf(w, f.x, sv[2 * k]);
                sv[2 * k + 1] = fmaf(w, f.y, sv[2 * k + 1]);
            }
        }
        #pragma unroll
        for (int k = 0; k < 8; k++) acc[k] = fmaf(a, sv[k], acc[k]);
    }

    uint4 o;
    o.x = cvt2(acc[0], acc[1]);
    o.y = cvt2(acc[2], acc[3]);
    o.z = cvt2(acc[4], acc[5]);
    o.w = cvt2(acc[6], acc[7]);
    *reinterpret_cast<uint4*>(&g_samp[(size_t)bq * CDIM + h * DD + c8]) = o;
}

// ---------------------------------------------------------------------------
// Launch: front-end fork; persistent (continuous-pipeline) PRE GEMMs.
// ---------------------------------------------------------------------------
extern "C" void kernel_launch(void* const* d_in, const int* in_sizes, int n_in,
                              void* d_out, int out_size)
{
    const float* query = (const float*)d_in[0];
    const float* refp  = (const float*)d_in[1];
    const float* inp   = (const float*)d_in[2];
    const float* w_val = (const float*)d_in[3];
    const float* b_val = (const float*)d_in[4];
    const float* w_off = (const float*)d_in[5];
    const float* b_off = (const float*)d_in[6];
    const float* w_att = (const float*)d_in[7];
    const float* b_att = (const float*)d_in[8];
    const float* w_out = (const float*)d_in[9];
    const float* b_out = (const float*)d_in[10];
    float* out = (float*)d_out;

    float* poa;
    cudaGetSymbolAddress((void**)&poa, g_oa);
    __half *pih, *pvh, *sp, *wv, *wo, *woa;
    cudaGetSymbolAddress((void**)&pih, g_inph);
    cudaGetSymbolAddress((void**)&pvh, g_valh);
    cudaGetSymbolAddress((void**)&sp, g_samp);
    cudaGetSymbolAddress((void**)&wv, g_wv);
    cudaGetSymbolAddress((void**)&wo, g_wo);
    cudaGetSymbolAddress((void**)&woa, g_woa);

    const int SMEM_NP  = 2 * 20480;   // 40 KB (2-stage)
    const int SMEM_PRE = 4 * 20480;   // 80 KB (4-stage)
    const int PERSIST_BLOCKS = 2 * 148;   // 2 blocks/SM x 148 SMs

    static bool init_done = false;
    static cudaStream_t s1;
    static cudaEvent_t evFork, evOA, evJoin;
    if (!init_done) {
        cudaFuncSetAttribute((const void*)gemm_mma<false, false>,
                             cudaFuncAttributeMaxDynamicSharedMemorySize, SMEM_NP);
        cudaFuncSetAttribute((const void*)gemm_mma<true, true>,
                             cudaFuncAttributeMaxDynamicSharedMemorySize, SMEM_PRE);
        cudaFuncSetAttribute((const void*)gemm_mma<true, false>,
                             cudaFuncAttributeMaxDynamicSharedMemorySize, SMEM_PRE);
        cudaStreamCreateWithFlags(&s1, cudaStreamNonBlocking);
        cudaEventCreateWithFlags(&evFork, cudaEventDisableTiming);
        cudaEventCreateWithFlags(&evOA, cudaEventDisableTiming);
        cudaEventCreateWithFlags(&evJoin, cudaEventDisableTiming);
        init_done = true;
    }

    const int Mv = N_B * LIN;   // 13824
    const int Mq = N_B * LQ;    // 32768

    // ---- fork side stream ----
    cudaEventRecord(evFork, 0);
    cudaStreamWaitEvent(s1, evFork, 0);

    // ---- s1: woa transposes + fused oa-GEMM ----
    transpose_h<<<dim3(CDIM / 32, 96 / 32), dim3(32, 8), 0, s1>>>(w_off, woa, CDIM, 96);
    transpose_h<<<dim3(CDIM / 32, 32 / 32), dim3(32, 8), 0, s1>>>(w_att, woa + 96 * CDIM, CDIM, 32);
    gemm_mma<false, false><<<dim3(1, Mq / 128), 256, SMEM_NP, s1>>>(
        query, nullptr, woa, b_off, b_att, 96, poa, Mq, 128, CDIM);
    cudaEventRecord(evOA, s1);

    // ---- s0: wv/wo transposes + f2h + value-GEMM (persistent) ----
    transpose_h2<<<dim3(CDIM / 32, CDIM / 32, 2), dim3(32, 8)>>>(w_val, wv, w_out, wo);
    f2h<<<(Mv * CDIM) / (256 * 8), 256>>>(inp, pih, Mv * CDIM);
    gemm_mma<true, true><<<PERSIST_BLOCKS, 256, SMEM_PRE>>>(
        nullptr, pih, wv, b_val, b_val, CDIM, pvh, Mv, CDIM, CDIM);

    // join: sampler needs oa (s1) and value (s0)
    cudaStreamWaitEvent(0, evOA, 0);

    // ---- sampler (serial, 384-thread blocks) ----
    sample_kernel<<<Mq / 4, 384>>>(refp);

    // ---- out-proj (persistent) ----
    gemm_mma<true, false><<<PERSIST_BLOCKS, 256, SMEM_PRE>>>(
        nullptr, sp, wo, b_out, b_out, CDIM, out, Mq, CDIM, CDIM);

    // keep stream graph well-formed
    cudaEventRecord(evJoin, 0);
    cudaStreamWaitEvent(s1, evJoin, 0);
}

// round 16
// speedup vs baseline: 1.1474x; 1.1474x over previous
#include <cuda_runtime.h>
#include <cuda_fp16.h>
#include <math.h>
#include <stdint.h>

// Problem constants
#define N_B 8
#define LQ 4096
#define CDIM 768
#define HH 8
#define PP 4
#define DD 96
#define LIN 1728
#define NVOX 12

// ---------------------------------------------------------------------------
// Scratch (static __device__ arrays: allocation-free, graph-capture safe)
// ---------------------------------------------------------------------------
__device__ __half g_inph[(size_t)N_B * LIN * CDIM];      // input_flatten (fp16)
__device__ __half g_valh[(size_t)N_B * LIN * CDIM];      // value (fp16) 21.2 MB
__device__ float g_oa[(size_t)N_B * LQ * 128];           // fused offsets(96)+attn(32)
__device__ __half g_samp[(size_t)N_B * LQ * CDIM];       // sampled (fp16)

// pre-transposed fp16 weights: [N][K]
__device__ __half g_wv[CDIM * CDIM];
__device__ __half g_wo[CDIM * CDIM];
__device__ __half g_woa[128 * CDIM];   // rows 0..95 = w_off, 96..127 = w_att

// ---------------------------------------------------------------------------
// PTX helpers (baseline ISA: ldmatrix + mma.sync + cp.async, sm_80+)
// ---------------------------------------------------------------------------
__device__ __forceinline__ uint32_t smem_u32(const void* p) {
    uint32_t a;
    asm("{ .reg .u64 t; cvta.to.shared.u64 t, %1; cvt.u32.u64 %0, t; }" : "=r"(a) : "l"(p));
    return a;
}
__device__ __forceinline__ void ldmx4(uint32_t& r0, uint32_t& r1, uint32_t& r2,
                                      uint32_t& r3, uint32_t addr) {
    asm volatile("ldmatrix.sync.aligned.m8n8.x4.shared.b16 {%0,%1,%2,%3}, [%4];"
                 : "=r"(r0), "=r"(r1), "=r"(r2), "=r"(r3) : "r"(addr));
}
__device__ __forceinline__ void mma16816(float* d, const uint32_t* a, const uint32_t* b) {
    asm volatile(
        "mma.sync.aligned.m16n8k16.row.col.f32.f16.f16.f32 "
        "{%0,%1,%2,%3}, {%4,%5,%6,%7}, {%8,%9}, {%0,%1,%2,%3};"
        : "+f"(d[0]), "+f"(d[1]), "+f"(d[2]), "+f"(d[3])
        : "r"(a[0]), "r"(a[1]), "r"(a[2]), "r"(a[3]), "r"(b[0]), "r"(b[1]));
}
__device__ __forceinline__ void cpasync16(uint32_t dst, const void* src) {
    asm volatile("cp.async.cg.shared.global [%0], [%1], 16;" :: "r"(dst), "l"(src));
}
#define CP_COMMIT() asm volatile("cp.async.commit_group;" ::: "memory")
#define CP_WAIT(n)  asm volatile("cp.async.wait_group %0;" :: "n"(n) : "memory")

__device__ __forceinline__ uint32_t cvt2(float x, float y) {
    __half2 h = __floats2half2_rn(x, y);
    return *reinterpret_cast<uint32_t*>(&h);
}

// ---------------------------------------------------------------------------
// Bulk fp32 -> fp16 convert (8 elems/thread, vectorized)
// ---------------------------------------------------------------------------
__global__ void f2h(const float* __restrict__ in, __half* __restrict__ out, int n)
{
    int i = (blockIdx.x * 256 + threadIdx.x) * 8;
    if (i >= n) return;
    float4 a = *reinterpret_cast<const float4*>(in + i);
    float4 b = *reinterpret_cast<const float4*>(in + i + 4);
    uint4 o;
    o.x = cvt2(a.x, a.y);
    o.y = cvt2(a.z, a.w);
    o.z = cvt2(b.x, b.y);
    o.w = cvt2(b.z, b.w);
    *reinterpret_cast<uint4*>(out + i) = o;
}

// ---------------------------------------------------------------------------
// Coalesced tiled transpose + fp16 convert: h[n*K+k] = (half)w[k*N+n]
// ---------------------------------------------------------------------------
__device__ __forceinline__ void transpose_body(const float* __restrict__ w,
                                               __half* __restrict__ h, int K, int N)
{
    __shared__ float tile[32][33];
    const int k0 = blockIdx.x * 32, n0 = blockIdx.y * 32;
    const int tx = threadIdx.x, ty = threadIdx.y;
    #pragma unroll
    for (int i = 0; i < 32; i += 8)
        tile[ty + i][tx] = w[(size_t)(k0 + ty + i) * N + n0 + tx];
    __syncthreads();
    #pragma unroll
    for (int i = 0; i < 32; i += 8)
        h[(size_t)(n0 + ty + i) * K + k0 + tx] = __float2half(tile[tx][ty + i]);
}
__global__ void transpose_h(const float* __restrict__ w, __half* __restrict__ h,
                            int K, int N)
{
    transpose_body(w, h, K, N);
}
__global__ void transpose_h2(const float* __restrict__ w0, __half* __restrict__ h0,
                             const float* __restrict__ w1, __half* __restrict__ h1)
{
    transpose_body(blockIdx.z ? w1 : w0, blockIdx.z ? h1 : h0, CDIM, CDIM);
}

// ---------------------------------------------------------------------------
// fp16 HMMA GEMM: C[M,128] = A[M,K] @ Bt[128,K]^T + bias
// BM=128, BN=128, BK=32; 256 threads = 4(m) x 2(n) warps; warp tile 32x64.
// PRE=false: A fp32, converted inline; B via cp.async (2-stage).
// PRE=true : A pre-converted fp16; 4-stage all-cp.async pipeline.
// ---------------------------------------------------------------------------
template <bool PRE, bool OUTH>
__global__ void __launch_bounds__(256, 2)
gemm_mma(const float* __restrict__ A32, const __half* __restrict__ Ah,
         const __half* __restrict__ Bt,
         const float* __restrict__ bias, const float* __restrict__ bias2, int nsplit,
         void* __restrict__ Cout, int M, int N, int K)
{
    constexpr int BM = 128, BN = 128, BK = 32, SA = 40;
    constexpr int WN = BN / 2, NF = WN / 8;
    constexpr int A_ELE = BM * SA;
    constexpr int B_ELE = BN * SA;
    constexpr int BUF = A_ELE + B_ELE;
    constexpr int STAGES = PRE ? 4 : 2;

    extern __shared__ __half smbuf[];
    const uint32_t sbase = smem_u32(smbuf);

    const int tid = threadIdx.x;
    const int lane = tid & 31;
    const int wid = tid >> 5;
    const int wm = wid & 3, wn = wid >> 2;
    const int bm = blockIdx.y * BM, bn = blockIdx.x * BN;
    const int nch = K / BK;

    float acc[2][NF][4];
    #pragma unroll
    for (int i = 0; i < 2; i++)
        #pragma unroll
        for (int j = 0; j < NF; j++)
            #pragma unroll
            for (int q = 0; q < 4; q++) acc[i][j][q] = 0.f;

    float4 aR[4];

    auto asyncB = [&](int c, int buf) {
        const int k0 = c * BK;
        const uint32_t base = sbase + (uint32_t)buf * BUF * 2;
        #pragma unroll
        for (int t = 0; t < 2; t++) {
            int l = t * 256 + tid;
            int rr = l >> 2, q = l & 3;
            uint32_t dst = base + (uint32_t)(A_ELE + rr * SA + q * 8) * 2;
            cpasync16(dst, &Bt[(size_t)(bn + rr) * K + k0 + q * 8]);
        }
    };
    auto asyncA = [&](int c, int buf) {
        const int k0 = c * BK;
        const uint32_t base = sbase + (uint32_t)buf * BUF * 2;
        #pragma unroll
        for (int t = 0; t < 2; t++) {
            int l = t * 256 + tid;
            int rr = l >> 2, q = l & 3;
            uint32_t dst = base + (uint32_t)(rr * SA + q * 8) * 2;
            cpasync16(dst, &Ah[(size_t)(bm + rr) * K + k0 + q * 8]);
        }
    };
    auto loadA = [&](int c) {
        const int k0 = c * BK;
        #pragma unroll
        for (int t = 0; t < 4; t++) {
            int l = t * 256 + tid;
            int row = l >> 3, c4 = l & 7;
            aR[t] = *reinterpret_cast<const float4*>(&A32[(size_t)(bm + row) * K + k0 + c4 * 4]);
        }
    };
    auto stsA = [&](int buf) {
        const uint32_t base = sbase + (uint32_t)buf * BUF * 2;
        #pragma unroll
        for (int t = 0; t < 4; t++) {
            int l = t * 256 + tid;
            int row = l >> 3, c4 = l & 7;
            uint32_t a01 = cvt2(aR[t].x, aR[t].y);
            uint32_t a23 = cvt2(aR[t].z, aR[t].w);
            uint32_t off = (uint32_t)(row * SA + c4 * 4) * 2;
            asm volatile("st.shared.v2.b32 [%0], {%1,%2};"
                         :: "r"(base + off), "r"(a01), "r"(a23) : "memory");
        }
    };
    auto compute = [&](int buf) {
        const uint32_t base = sbase + (uint32_t)buf * BUF * 2;
        const uint32_t aS = base;
        const uint32_t bS = base + A_ELE * 2;
        #pragma unroll
        for (int s = 0; s < 2; s++) {
            uint32_t ah[2][4], bh[NF][2];
            #pragma unroll
            for (int i = 0; i < 2; i++) {
                uint32_t row = wm * 32 + i * 16 + (lane & 15);
                uint32_t off = (row * SA + s * 16 + (lane >> 4) * 8) * 2;
                ldmx4(ah[i][0], ah[i][1], ah[i][2], ah[i][3], aS + off);
            }
            #pragma unroll
            for (int j = 0; j < NF; j += 2) {
                uint32_t row = wn * WN + j * 8 + (lane & 7) + ((lane & 16) ? 8 : 0);
                uint32_t off = (row * SA + s * 16 + ((lane >> 3) & 1) * 8) * 2;
                ldmx4(bh[j][0], bh[j][1], bh[j + 1][0], bh[j + 1][1], bS + off);
            }
            #pragma unroll
            for (int i = 0; i < 2; i++)
                #pragma unroll
                for (int j = 0; j < NF; j++)
                    mma16816(acc[i][j], ah[i], bh[j]);
        }
    };

    if constexpr (PRE) {
        #pragma unroll
        for (int i = 0; i < STAGES - 1; i++) {
            asyncA(i, i); asyncB(i, i); CP_COMMIT();
        }
        for (int c = 0; c < nch; c++) {
            CP_WAIT(STAGES - 2);
            __syncthreads();
            int f = c + STAGES - 1;
            if (f < nch) { asyncA(f, f % STAGES); asyncB(f, f % STAGES); }
            CP_COMMIT();
            compute(c % STAGES);
        }
    } else {
        asyncB(0, 0); CP_COMMIT();
        loadA(0);
        CP_WAIT(0);
        stsA(0);
        __syncthreads();
        for (int c = 0; c < nch; c++) {
            if (c + 1 < nch) { asyncB(c + 1, (c + 1) & 1); CP_COMMIT(); loadA(c + 1); }
            compute(c & 1);
            if (c + 1 < nch) { CP_WAIT(0); stsA((c + 1) & 1); }
            __syncthreads();
        }
    }

    #pragma unroll
    for (int i = 0; i < 2; i++) {
        int r0 = bm + wm * 32 + i * 16 + (lane >> 2);
        #pragma unroll
        for (int j = 0; j < NF; j++) {
            int col = bn + wn * WN + j * 8 + (lane & 3) * 2;
            float b0 = (col < nsplit) ? bias[col] : bias2[col - nsplit];
            float b1 = (col + 1 < nsplit) ? bias[col + 1] : bias2[col + 1 - nsplit];
            if constexpr (OUTH) {
                __half* C = (__half*)Cout;
                uint32_t v0 = cvt2(acc[i][j][0] + b0, acc[i][j][1] + b1);
                uint32_t v1 = cvt2(acc[i][j][2] + b0, acc[i][j][3] + b1);
                *reinterpret_cast<uint32_t*>(&C[(size_t)r0 * N + col]) = v0;
                *reinterpret_cast<uint32_t*>(&C[(size_t)(r0 + 8) * N + col]) = v1;
            } else {
                float* C = (float*)Cout;
                float2 v0 = make_float2(acc[i][j][0] + b0, acc[i][j][1] + b1);
                float2 v1 = make_float2(acc[i][j][2] + b0, acc[i][j][3] + b1);
                *reinterpret_cast<float2*>(&C[(size_t)r0 * N + col]) = v0;
                *reinterpret_cast<float2*>(&C[(size_t)(r0 + 8) * N + col]) = v1;
            }
        }
    }
}

// ---------------------------------------------------------------------------
// Sampler: 384 threads = 4 queries x 96 gather threads (uint4 = 8 fp16 ch).
// ---------------------------------------------------------------------------
__global__ void __launch_bounds__(384) sample_kernel(const float* __restrict__ refpts)
{
    const int b0 = blockIdx.x * 4;

    __shared__ float s_attn[4][32];
    __shared__ int   s_idx[4][32][8];
    __shared__ float s_w[4][32][8];

    const int tid = threadIdx.x;

    if (tid < 128) {
        int qi = tid >> 5, hp = tid & 31;
        int bq = b0 + qi;
        const float* oa = &g_oa[(size_t)bq * 128 + hp * 3];
        float rx = refpts[(size_t)bq * 3 + 0];
        float ry = refpts[(size_t)bq * 3 + 1];
        float rz = refpts[(size_t)bq * 3 + 2];
        float x = 12.f * rx + oa[0] - 0.5f;
        float y = 12.f * ry + oa[1] - 0.5f;
        float z = 12.f * rz + oa[2] - 0.5f;
        float x0f = floorf(x), y0f = floorf(y), z0f = floorf(z);
        int x0 = (int)x0f, y0 = (int)y0f, z0 = (int)z0f;
        float fx = x - x0f, fy = y - y0f, fz = z - z0f;
        #pragma unroll
        for (int c = 0; c < 8; c++) {
            int dx = c & 1, dy = (c >> 1) & 1, dz = (c >> 2) & 1;
            int xi = x0 + dx, yi = y0 + dy, zi = z0 + dz;
            float w = (dx ? fx : 1.f - fx) * (dy ? fy : 1.f - fy) * (dz ? fz : 1.f - fz);
            bool valid = (xi >= 0) & (xi < NVOX) & (yi >= 0) & (yi < NVOX) &
                         (zi >= 0) & (zi < NVOX);
            int xc = min(max(xi, 0), NVOX - 1);
            int yc = min(max(yi, 0), NVOX - 1);
            int zc = min(max(zi, 0), NVOX - 1);
            s_idx[qi][hp][c] = (zc * NVOX + yc) * NVOX + xc;
            s_w[qi][hp][c] = valid ? w : 0.f;
        }
    }
    if (tid >= 128 && tid < 160) {
        int idx = tid - 128;
        int qi = idx >> 3, h = idx & 7;
        const float* lg = &g_oa[(size_t)(b0 + qi) * 128 + 96 + h * 4];
        float m = fmaxf(fmaxf(lg[0], lg[1]), fmaxf(lg[2], lg[3]));
        float e0 = expf(lg[0] - m), e1 = expf(lg[1] - m);
        float e2 = expf(lg[2] - m), e3 = expf(lg[3] - m);
        float inv = 1.f / (e0 + e1 + e2 + e3);
        s_attn[qi][h * 4 + 0] = e0 * inv;
        s_attn[qi][h * 4 + 1] = e1 * inv;
        s_attn[qi][h * 4 + 2] = e2 * inv;
        s_attn[qi][h * 4 + 3] = e3 * inv;
    }
    __syncthreads();

    const int qi = tid / 96;
    const int tt = tid % 96;
    const int h = tt / 12;
    const int c8 = (tt % 12) * 8;
    const int bq = b0 + qi;
    const int n = bq >> 12;
    const __half* vbase = &g_valh[(size_t)n * LIN * CDIM + h * DD + c8];

    float acc[8];
    #pragma unroll
    for (int k = 0; k < 8; k++) acc[k] = 0.f;

    #pragma unroll
    for (int p = 0; p < PP; p++) {
        int hp = h * PP + p;
        float a = s_attn[qi][hp];
        float sv[8];
        #pragma unroll
        for (int k = 0; k < 8; k++) sv[k] = 0.f;
        #pragma unroll
        for (int c = 0; c < 8; c++) {
            float w = s_w[qi][hp][c];
            uint4 v = *reinterpret_cast<const uint4*>(
                vbase + (size_t)s_idx[qi][hp][c] * CDIM);
            const __half2* hv = reinterpret_cast<const __half2*>(&v);
            #pragma unroll
            for (int k = 0; k < 4; k++) {
                float2 f = __half22float2(hv[k]);
                sv[2 * k]     = fmaf(w, f.x, sv[2 * k]);
                sv[2 * k + 1] = fmaf(w, f.y, sv[2 * k + 1]);
            }
        }
        #pragma unroll
        for (int k = 0; k < 8; k++) acc[k] = fmaf(a, sv[k], acc[k]);
    }

    uint4 o;
    o.x = cvt2(acc[0], acc[1]);
    o.y = cvt2(acc[2], acc[3]);
    o.z = cvt2(acc[4], acc[5]);
    o.w = cvt2(acc[6], acc[7]);
    *reinterpret_cast<uint4*>(&g_samp[(size_t)bq * CDIM + h * DD + c8]) = o;
}

// ---------------------------------------------------------------------------
// Launch: front-end fork with transpose_h2 moved off the s0 critical path.
// ---------------------------------------------------------------------------
extern "C" void kernel_launch(void* const* d_in, const int* in_sizes, int n_in,
                              void* d_out, int out_size)
{
    const float* query = (const float*)d_in[0];
    const float* refp  = (const float*)d_in[1];
    const float* inp   = (const float*)d_in[2];
    const float* w_val = (const float*)d_in[3];
    const float* b_val = (const float*)d_in[4];
    const float* w_off = (const float*)d_in[5];
    const float* b_off = (const float*)d_in[6];
    const float* w_att = (const float*)d_in[7];
    const float* b_att = (const float*)d_in[8];
    const float* w_out = (const float*)d_in[9];
    const float* b_out = (const float*)d_in[10];
    float* out = (float*)d_out;

    float* poa;
    cudaGetSymbolAddress((void**)&poa, g_oa);
    __half *pih, *pvh, *sp, *wv, *wo, *woa;
    cudaGetSymbolAddress((void**)&pih, g_inph);
    cudaGetSymbolAddress((void**)&pvh, g_valh);
    cudaGetSymbolAddress((void**)&sp, g_samp);
    cudaGetSymbolAddress((void**)&wv, g_wv);
    cudaGetSymbolAddress((void**)&wo, g_wo);
    cudaGetSymbolAddress((void**)&woa, g_woa);

    const int SMEM_NP  = 2 * 20480;   // 40 KB (2-stage)
    const int SMEM_PRE = 4 * 20480;   // 80 KB (4-stage)

    static bool init_done = false;
    static cudaStream_t s1;
    static cudaEvent_t evFork, evW, evOA, evJoin;
    if (!init_done) {
        cudaFuncSetAttribute((const void*)gemm_mma<false, false>,
                             cudaFuncAttributeMaxDynamicSharedMemorySize, SMEM_NP);
        cudaFuncSetAttribute((const void*)gemm_mma<true, true>,
                             cudaFuncAttributeMaxDynamicSharedMemorySize, SMEM_PRE);
        cudaFuncSetAttribute((const void*)gemm_mma<true, false>,
                             cudaFuncAttributeMaxDynamicSharedMemorySize, SMEM_PRE);
        cudaStreamCreateWithFlags(&s1, cudaStreamNonBlocking);
        cudaEventCreateWithFlags(&evFork, cudaEventDisableTiming);
        cudaEventCreateWithFlags(&evW, cudaEventDisableTiming);
        cudaEventCreateWithFlags(&evOA, cudaEventDisableTiming);
        cudaEventCreateWithFlags(&evJoin, cudaEventDisableTiming);
        init_done = true;
    }

    const int Mv = N_B * LIN;   // 13824
    const int Mq = N_B * LQ;    // 32768

    // ---- fork side stream ----
    cudaEventRecord(evFork, 0);
    cudaStreamWaitEvent(s1, evFork, 0);

    // ---- s1: wv/wo transposes first (off s0 critical path), then woa + oa-GEMM
    transpose_h2<<<dim3(CDIM / 32, CDIM / 32, 2), dim3(32, 8), 0, s1>>>(w_val, wv, w_out, wo);
    cudaEventRecord(evW, s1);
    transpose_h<<<dim3(CDIM / 32, 96 / 32), dim3(32, 8), 0, s1>>>(w_off, woa, CDIM, 96);
    transpose_h<<<dim3(CDIM / 32, 32 / 32), dim3(32, 8), 0, s1>>>(w_att, woa + 96 * CDIM, CDIM, 32);
    gemm_mma<false, false><<<dim3(1, Mq / 128), 256, SMEM_NP, s1>>>(
        query, nullptr, woa, b_off, b_att, 96, poa, Mq, 128, CDIM);
    cudaEventRecord(evOA, s1);

    // ---- s0: f2h immediately; wait for wv before value-GEMM ----
    f2h<<<(Mv * CDIM) / (256 * 8), 256>>>(inp, pih, Mv * CDIM);
    cudaStreamWaitEvent(0, evW, 0);
    gemm_mma<true, true><<<dim3(CDIM / 128, Mv / 128), 256, SMEM_PRE>>>(
        nullptr, pih, wv, b_val, b_val, CDIM, pvh, Mv, CDIM, CDIM);

    // join: sampler needs oa (s1) and value (s0)
    cudaStreamWaitEvent(0, evOA, 0);

    // ---- sampler (serial, 384-thread blocks) ----
    sample_kernel<<<Mq / 4, 384>>>(refp);

    // ---- out-proj (2D grid, round-13 form) ----
    gemm_mma<true, false><<<dim3(CDIM / 128, Mq / 128), 256, SMEM_PRE>>>(
        nullptr, sp, wo, b_out, b_out, CDIM, out, Mq, CDIM, CDIM);

    // keep stream graph well-formed
    cudaEventRecord(evJoin, 0);
    cudaStreamWaitEvent(s1, evJoin, 0);
}